// round 2
// baseline (speedup 1.0000x reference)
#include <cuda_runtime.h>

// ---------------------------------------------------------------------------
// SMPL fused pipeline, round 2: f32x2 packed-FFMA GEMMs.
// Inputs (metadata order):
//  0 beta (1024,10)  1 theta (1024,72)  2 trans (1024,3)
//  3 v_template (6890,3)  4 shapedirs (10,20670)  5 J_regressor (6890,24)
//  6 posedirs (207,20670)  7 joint_regressor (6890,19)  8 weights (6890,24)
// Output: joints (1024,19,3) float32
// ---------------------------------------------------------------------------

namespace smpl {

constexpr int V    = 6890;
constexpr int NB   = 10;
constexpr int NJ   = 24;
constexpr int NK   = 19;
constexpr int B    = 1024;

constexpr int VP   = 6912;            // V padded
constexpr int M1   = 512;             // 456 G rows + 24 Jreg rows + pad
constexpr int N1   = 768;             // 621 posedirs + 30 shapedirs + 3 tpl + 1 ones + pad
constexpr int SPLITK1 = 16;           // 6912/16 = 432 = 27*16
constexpr int KQ   = 224;             // 1 + 10 + 207, padded
constexpr int N2   = 1408;            // 456*3 = 1368, padded (11*128)
constexpr int SPLITK2 = 2;            // 224/2 = 112 = 7*16
constexpr int PSTR = B * N2;

__device__ __align__(256) float g_E  [VP * N1];
__device__ __align__(256) float g_G  [VP * M1];
__device__ __align__(256) float g_Cp [SPLITK1 * M1 * N1];
__device__ __align__(256) float g_CT [KQ * N2];
__device__ __align__(256) float g_S  [456];
__device__ __align__(256) float g_JT [24 * 33];
__device__ __align__(256) float g_A2T[KQ * B];
__device__ __align__(256) float g_Rg [B * 288];
__device__ __align__(256) float g_P  [SPLITK2 * B * N2];

__constant__ int c_par[24] = {-1,0,0,0,1,2,3,4,5,6,7,8,9,9,9,12,13,14,16,17,18,19,20,21};

// ------------------------------ f32x2 helpers ------------------------------
__device__ __forceinline__ unsigned long long pack2(float x, float y) {
    unsigned long long r;
    asm("mov.b64 %0, {%1, %2};" : "=l"(r) : "f"(x), "f"(y));
    return r;
}
__device__ __forceinline__ void ffma2(unsigned long long& d,
                                      unsigned long long a,
                                      unsigned long long b) {
    asm("fma.rn.f32x2 %0, %1, %2, %0;" : "+l"(d) : "l"(a), "l"(b));
}
__device__ __forceinline__ float2 unpack2(unsigned long long v) {
    float2 r;
    asm("mov.b64 {%0, %1}, %2;" : "=f"(r.x), "=f"(r.y) : "l"(v));
    return r;
}

// ---------------------------------------------------------------------------
// buildE part 1: posedirs^T -> g_E[v][3p+c] for col<621, via smem transpose.
// Tile: 32 p x 32 v. Reads coalesced along v, writes coalesced along col.
// ---------------------------------------------------------------------------
__global__ void k_buildE_pose(const float* __restrict__ posedirs) {
    __shared__ float sm[32 * 97];
    const int v0 = blockIdx.x * 32;
    const int p0 = blockIdx.y * 32;
    const int tx = threadIdx.x & 31;
    const int ty = threadIdx.x >> 5;    // 0..7

#pragma unroll
    for (int s = 0; s < 4; ++s) {
        int pp = ty + 8 * s;            // 0..31 local p
        int p = p0 + pp;
        int v = v0 + tx;
        if (p < 207 && v < V) {
            const float* src = posedirs + (size_t)p * (V * 3) + 3 * v;
#pragma unroll
            for (int c = 0; c < 3; ++c)
                sm[tx * 97 + 3 * pp + c] = src[c];
        }
    }
    __syncthreads();
#pragma unroll
    for (int s = 0; s < 4; ++s) {
        int vv = ty + 8 * s;
        int v = v0 + vv;
        if (v < V) {
#pragma unroll
            for (int c = 0; c < 3; ++c) {
                int col = 3 * p0 + 3 * tx + c;
                if (col < 621)
                    g_E[(size_t)v * N1 + col] = sm[vv * 97 + 3 * tx + c];
            }
        }
    }
}

// buildE part 2: cols [621,768) for all VP rows (shapedirs/template/ones/pad)
__global__ void k_buildE_rest(const float* __restrict__ shapedirs,
                              const float* __restrict__ v_template) {
    int idx = blockIdx.x * blockDim.x + threadIdx.x;
    if (idx >= VP * 147) return;
    int v = idx / 147, col = 621 + (idx - v * 147);
    float val = 0.f;
    if (v < V) {
        if (col < 651) {
            int t = col - 621, n = t / 3, c = t - 3 * n;
            val = shapedirs[n * (V * 3) + 3 * v + c];
        } else if (col < 654) {
            val = v_template[v * 3 + (col - 651)];
        } else if (col == 654) {
            val = 1.f;
        }
    }
    g_E[(size_t)v * N1 + col] = val;
}

// buildE part 3: zero rows v in [V,VP) for cols [0,621)
__global__ void k_buildE_padrows() {
    int idx = blockIdx.x * blockDim.x + threadIdx.x;
    if (idx >= (VP - V) * 621) return;
    int v = V + idx / 621, col = idx - (idx / 621) * 621;
    g_E[(size_t)v * N1 + col] = 0.f;
}

// ---------------------------------------------------------------------------
// buildG: G[v][row]; row<456: jr[v,row/24]*w[v,row%24]; 456..479: Jreg
// ---------------------------------------------------------------------------
__global__ void k_buildG(const float* __restrict__ jr19,
                         const float* __restrict__ w24,
                         const float* __restrict__ Jreg24) {
    int idx = blockIdx.x * blockDim.x + threadIdx.x;
    if (idx >= VP * M1) return;
    int v = idx / M1, row = idx - v * M1;
    float val = 0.f;
    if (v < V) {
        if (row < 456) {
            int k = row / 24, j = row - 24 * k;
            val = jr19[v * NK + k] * w24[v * NJ + j];
        } else if (row < 480) {
            val = Jreg24[v * NJ + (row - 456)];
        }
    }
    g_G[idx] = val;
}

// ---------------------------------------------------------------------------
// 128x128-tile GEMM with packed f32x2 FMAs.
//   C[M x N] (split-K partials): A is K-major [K][lda] (=A^T), B [K][ldb].
//   256 threads, 8x8 per-thread tile, BK=16, register prefetch.
// ---------------------------------------------------------------------------
__global__ void __launch_bounds__(256)
k_gemm128(const float* __restrict__ A, int lda,
          const float* __restrict__ B, int ldb,
          float* __restrict__ C, int ldc,
          int kPerSplit, int cSplitStride) {
    const int split = blockIdx.z;
    const int row0 = blockIdx.y * 128;
    const int col0 = blockIdx.x * 128;
    const float* Ak = A + (size_t)split * kPerSplit * lda;
    const float* Bk = B + (size_t)split * kPerSplit * ldb;
    float* Co = C + (size_t)split * cSplitStride;

    __shared__ __align__(16) float As[16][128];
    __shared__ __align__(16) float Bs[16][128];

    const int tid = threadIdx.x;
    const int lk = tid >> 4;            // 0..15 k-row for loads
    const int lo = (tid & 15) << 3;     // 0..120 offset for loads
    const int tm = (tid >> 4) << 3;     // 0..120 m-base for compute
    const int tn = (tid & 15) << 3;     // 0..120 n-base for compute

    unsigned long long acc[8][4] = {};

    const int nIter = kPerSplit >> 4;
    float4 ra0 = *(const float4*)&Ak[(size_t)lk * lda + row0 + lo];
    float4 ra1 = *(const float4*)&Ak[(size_t)lk * lda + row0 + lo + 4];
    float4 rb0 = *(const float4*)&Bk[(size_t)lk * ldb + col0 + lo];
    float4 rb1 = *(const float4*)&Bk[(size_t)lk * ldb + col0 + lo + 4];

    for (int it = 0; it < nIter; ++it) {
        __syncthreads();
        *(float4*)&As[lk][lo]     = ra0;
        *(float4*)&As[lk][lo + 4] = ra1;
        *(float4*)&Bs[lk][lo]     = rb0;
        *(float4*)&Bs[lk][lo + 4] = rb1;
        __syncthreads();
        if (it + 1 < nIter) {
            size_t kb = (size_t)((it + 1) * 16 + lk);
            ra0 = *(const float4*)&Ak[kb * lda + row0 + lo];
            ra1 = *(const float4*)&Ak[kb * lda + row0 + lo + 4];
            rb0 = *(const float4*)&Bk[kb * ldb + col0 + lo];
            rb1 = *(const float4*)&Bk[kb * ldb + col0 + lo + 4];
        }
#pragma unroll
        for (int p = 0; p < 16; ++p) {
            float4 a0 = *(const float4*)&As[p][tm];
            float4 a1 = *(const float4*)&As[p][tm + 4];
            float4 b0 = *(const float4*)&Bs[p][tn];
            float4 b1 = *(const float4*)&Bs[p][tn + 4];
            unsigned long long ad[8];
            ad[0] = pack2(a0.x, a0.x); ad[1] = pack2(a0.y, a0.y);
            ad[2] = pack2(a0.z, a0.z); ad[3] = pack2(a0.w, a0.w);
            ad[4] = pack2(a1.x, a1.x); ad[5] = pack2(a1.y, a1.y);
            ad[6] = pack2(a1.z, a1.z); ad[7] = pack2(a1.w, a1.w);
            unsigned long long bp[4];
            bp[0] = pack2(b0.x, b0.y); bp[1] = pack2(b0.z, b0.w);
            bp[2] = pack2(b1.x, b1.y); bp[3] = pack2(b1.z, b1.w);
#pragma unroll
            for (int i = 0; i < 8; ++i)
#pragma unroll
                for (int j = 0; j < 4; ++j)
                    ffma2(acc[i][j], ad[i], bp[j]);
        }
    }

#pragma unroll
    for (int i = 0; i < 8; ++i) {
        float2 p0 = unpack2(acc[i][0]);
        float2 p1 = unpack2(acc[i][1]);
        float2 p2 = unpack2(acc[i][2]);
        float2 p3 = unpack2(acc[i][3]);
        float* dst = &Co[(size_t)(row0 + tm + i) * ldc + col0 + tn];
        *(float4*)dst       = make_float4(p0.x, p0.y, p1.x, p1.y);
        *(float4*)(dst + 4) = make_float4(p2.x, p2.y, p3.x, p3.y);
    }
}

// ---------------------------------------------------------------------------
// Reduce GEMM1 split-K partials into CT [q][m], S, JT.
// ---------------------------------------------------------------------------
__global__ void k_reduce() {
    int idx = blockIdx.x * blockDim.x + threadIdx.x;
    const int NCT = KQ * N2;
    if (idx < NCT) {
        int q = idx / N2, m = idx - q * N2;
        float val = 0.f;
        if (m < 1368 && q < 218) {
            int kj = m / 3, c = m - 3 * kj;
            int col;
            if (q == 0)        col = 651 + c;
            else if (q <= 10)  col = 621 + (q - 1) * 3 + c;
            else               col = (q - 11) * 3 + c;
            size_t off = (size_t)kj * N1 + col;
#pragma unroll
            for (int s = 0; s < SPLITK1; ++s)
                val += g_Cp[(size_t)s * (M1 * N1) + off];
        }
        g_CT[idx] = val;
    } else if (idx < NCT + 456) {
        int kj = idx - NCT;
        float val = 0.f;
#pragma unroll
        for (int s = 0; s < SPLITK1; ++s)
            val += g_Cp[(size_t)s * (M1 * N1) + (size_t)kj * N1 + 654];
        g_S[kj] = val;
    } else if (idx < NCT + 456 + 24 * 33) {
        int t2 = idx - NCT - 456;
        int j = t2 / 33, t = t2 - 33 * j;
        float val = 0.f;
#pragma unroll
        for (int s = 0; s < SPLITK1; ++s)
            val += g_Cp[(size_t)s * (M1 * N1) + (size_t)(456 + j) * N1 + 621 + t];
        g_JT[t2] = val;
    }
}

// ---------------------------------------------------------------------------
// Per-body prep (one warp / body): Rodrigues, J, A2T column, kinematic chain.
// ---------------------------------------------------------------------------
__global__ void k_prep(const float* __restrict__ beta,
                       const float* __restrict__ theta) {
    const int b = blockIdx.x;
    const int lane = threadIdx.x;

    __shared__ float Rsm[24][9];
    __shared__ float Jm[24][3];
    __shared__ float Ag[24][12];
    __shared__ float bet[10];

    if (lane < 10) bet[lane] = beta[b * NB + lane];
    __syncwarp();

    if (lane < 24) {
        float tx = theta[b * 72 + lane * 3 + 0];
        float ty = theta[b * 72 + lane * 3 + 1];
        float tz = theta[b * 72 + lane * 3 + 2];
        float ax = tx + 1e-8f, ay = ty + 1e-8f, az = tz + 1e-8f;
        float angle = sqrtf(ax * ax + ay * ay + az * az);
        float half = 0.5f * angle;
        float s = sinf(half), cw = cosf(half);
        float vx = tx / angle * s, vy = ty / angle * s, vz = tz / angle * s;
        float qn = sqrtf(cw * cw + vx * vx + vy * vy + vz * vz);
        float w = cw / qn, x = vx / qn, y = vy / qn, z = vz / qn;
        Rsm[lane][0] = 1.f - 2.f * (y * y + z * z);
        Rsm[lane][1] = 2.f * (x * y - w * z);
        Rsm[lane][2] = 2.f * (x * z + w * y);
        Rsm[lane][3] = 2.f * (x * y + w * z);
        Rsm[lane][4] = 1.f - 2.f * (x * x + z * z);
        Rsm[lane][5] = 2.f * (y * z - w * x);
        Rsm[lane][6] = 2.f * (x * z - w * y);
        Rsm[lane][7] = 2.f * (y * z + w * x);
        Rsm[lane][8] = 1.f - 2.f * (x * x + y * y);
#pragma unroll
        for (int c = 0; c < 3; ++c) {
            float val = g_JT[lane * 33 + 30 + c];
#pragma unroll
            for (int n = 0; n < 10; ++n)
                val += bet[n] * g_JT[lane * 33 + n * 3 + c];
            Jm[lane][c] = val;
        }
    }
    __syncwarp();

    for (int q = lane; q < KQ; q += 32) {
        float val;
        if (q == 0) val = 1.f;
        else if (q <= 10) val = bet[q - 1];
        else if (q < 218) {
            int p = q - 11;
            int i = p / 9 + 1, e = p - 9 * (p / 9);
            val = Rsm[i][e] - ((e == 0 || e == 4 || e == 8) ? 1.f : 0.f);
        } else val = 0.f;
        g_A2T[q * B + b] = val;
    }

    const int r = lane >> 2, cc = lane & 3;
    for (int i = 0; i < 24; ++i) {
        if (lane < 12) {
            float val;
            if (i == 0) {
                val = (cc < 3) ? Rsm[0][r * 3 + cc] * (cc == 0 ? 1.f : -1.f)
                               : Jm[0][r];
            } else {
                int par = c_par[i];
                float l0, l1, l2;
                if (cc < 3) {
                    l0 = Rsm[i][0 * 3 + cc];
                    l1 = Rsm[i][1 * 3 + cc];
                    l2 = Rsm[i][2 * 3 + cc];
                } else {
                    l0 = Jm[i][0] - Jm[par][0];
                    l1 = Jm[i][1] - Jm[par][1];
                    l2 = Jm[i][2] - Jm[par][2];
                }
                val = Ag[par][r * 4 + 0] * l0 + Ag[par][r * 4 + 1] * l1 +
                      Ag[par][r * 4 + 2] * l2;
                if (cc == 3) val += Ag[par][r * 4 + 3];
            }
            Ag[i][r * 4 + cc] = val;
        }
        __syncwarp();
    }

    for (int idx = lane; idx < 288; idx += 32) {
        int j = idx / 12, e = idx - 12 * j;
        float out;
        if (e < 9) {
            int rr = e / 3, c = e - 3 * rr;
            out = Ag[j][rr * 4 + c];
        } else {
            int rr = e - 9;
            out = Ag[j][rr * 4 + 3] -
                  (Ag[j][rr * 4 + 0] * Jm[j][0] + Ag[j][rr * 4 + 1] * Jm[j][1] +
                   Ag[j][rr * 4 + 2] * Jm[j][2]);
        }
        g_Rg[b * 288 + idx] = out;
    }
}

// ---------------------------------------------------------------------------
// joints epilogue (sums the two GEMM2 split-K partials in-place)
// ---------------------------------------------------------------------------
__global__ void k_joints(const float* __restrict__ trans,
                         float* __restrict__ out) {
    const int b = blockIdx.x;
    const int tid = threadIdx.x;
    __shared__ float sA[288];
    __shared__ float sS[456];
    for (int i = tid; i < 288; i += 64) sA[i] = g_Rg[b * 288 + i];
    for (int i = tid; i < 456; i += 64) sS[i] = g_S[i];
    __syncthreads();
    if (tid < 57) {
        int k = tid / 3, r = tid - 3 * k;
        float acc = trans[b * 3 + r];
        const float* Pb0 = &g_P[(size_t)b * N2];
        const float* Pb1 = &g_P[(size_t)PSTR + (size_t)b * N2];
#pragma unroll
        for (int j = 0; j < 24; ++j) {
            const float* M = &sA[j * 12];
            int m = (k * 24 + j) * 3;
            float p0 = Pb0[m + 0] + Pb1[m + 0];
            float p1 = Pb0[m + 1] + Pb1[m + 1];
            float p2 = Pb0[m + 2] + Pb1[m + 2];
            acc += M[r * 3 + 0] * p0 + M[r * 3 + 1] * p1 + M[r * 3 + 2] * p2 +
                   M[9 + r] * sS[k * 24 + j];
        }
        out[b * 57 + tid] = acc;
    }
}

} // namespace smpl

extern "C" void kernel_launch(void* const* d_in, const int* in_sizes, int n_in,
                              void* d_out, int out_size) {
    using namespace smpl;
    const float* beta       = (const float*)d_in[0];
    const float* theta      = (const float*)d_in[1];
    const float* trans      = (const float*)d_in[2];
    const float* v_template = (const float*)d_in[3];
    const float* shapedirs  = (const float*)d_in[4];
    const float* J_reg      = (const float*)d_in[5];
    const float* posedirs   = (const float*)d_in[6];
    const float* joint_reg  = (const float*)d_in[7];
    const float* weights    = (const float*)d_in[8];
    float* out = (float*)d_out;

    float *pE, *pG, *pCp, *pCT, *pA2T, *pP;
    cudaGetSymbolAddress((void**)&pE,   g_E);
    cudaGetSymbolAddress((void**)&pG,   g_G);
    cudaGetSymbolAddress((void**)&pCp,  g_Cp);
    cudaGetSymbolAddress((void**)&pCT,  g_CT);
    cudaGetSymbolAddress((void**)&pA2T, g_A2T);
    cudaGetSymbolAddress((void**)&pP,   g_P);

    // 1) Build E (three regions) and G
    {
        dim3 grid((V + 31) / 32, (207 + 31) / 32);
        k_buildE_pose<<<grid, 256>>>(posedirs);
    }
    {
        int n = VP * 147;
        k_buildE_rest<<<(n + 255) / 256, 256>>>(shapedirs, v_template);
    }
    {
        int n = (VP - V) * 621;
        k_buildE_padrows<<<(n + 255) / 256, 256>>>();
    }
    {
        int n = VP * M1;
        k_buildG<<<(n + 255) / 256, 256>>>(joint_reg, weights, J_reg);
    }

    // 2) GEMM1: Cp[s] = G^T @ E, split-K = 16
    {
        dim3 grid(N1 / 128, M1 / 128, SPLITK1);   // 6 x 4 x 16
        k_gemm128<<<grid, 256>>>(pG, M1, pE, N1, pCp, N1, VP / SPLITK1, M1 * N1);
    }

    // 3) Reduce partials -> CT / S / JT
    {
        int n = KQ * N2 + 456 + 24 * 33;
        k_reduce<<<(n + 255) / 256, 256>>>();
    }

    // 4) Per-body prep
    k_prep<<<B, 32>>>(beta, theta);

    // 5) GEMM2: P[s] = A2 @ CT, split-K = 2
    {
        dim3 grid(N2 / 128, B / 128, SPLITK2);    // 11 x 8 x 2
        k_gemm128<<<grid, 256>>>(pA2T, B, pCT, N2, pP, N2, KQ / SPLITK2, PSTR);
    }

    // 6) Joints epilogue (folds the 2 partials)
    k_joints<<<B, 64>>>(trans, out);
}

// round 4
// speedup vs baseline: 1.5597x; 1.5597x over previous
#include <cuda_runtime.h>
#include <cuda_bf16.h>
#include <mma.h>
#include <cstdint>

// ---------------------------------------------------------------------------
// SMPL fused pipeline, round 4: GEMM1 on WMMA bf16 (fp32 acc), bf16x3 emu.
// Inputs (metadata order):
//  0 beta (1024,10)  1 theta (1024,72)  2 trans (1024,3)
//  3 v_template (6890,3)  4 shapedirs (10,20670)  5 J_regressor (6890,24)
//  6 posedirs (207,20670)  7 joint_regressor (6890,19)  8 weights (6890,24)
// Output: joints (1024,19,3) float32
// ---------------------------------------------------------------------------

namespace smpl {

constexpr int V    = 6890;
constexpr int NB   = 10;
constexpr int NJ   = 24;
constexpr int NK   = 19;
constexpr int B    = 1024;

constexpr int VP   = 6912;            // V padded (mult of 64)
constexpr int M1   = 512;             // 456 G rows + 24 Jreg rows + pad
constexpr int N1   = 768;             // 621 posedirs + 30 shapedirs + 3 tpl + 1 ones + pad
constexpr int SPLITK1 = 6;            // 6912/6 = 1152 = 36*32
constexpr int KSEG = VP / SPLITK1;    // 1152
constexpr int KQ   = 224;             // 1 + 10 + 207, padded
constexpr int N2   = 1408;            // 456*3 = 1368, padded

// bf16 hi/lo split operands for GEMM1 (row-major, K(=v) contiguous)
__device__ __align__(256) __nv_bfloat16 g_Gh[M1 * VP];
__device__ __align__(256) __nv_bfloat16 g_Gl[M1 * VP];
__device__ __align__(256) __nv_bfloat16 g_Eh[N1 * VP];
__device__ __align__(256) __nv_bfloat16 g_El[N1 * VP];

__device__ __align__(256) float g_Cp [SPLITK1 * M1 * N1];
__device__ __align__(256) float g_CT [KQ * N2];
__device__ __align__(256) float g_S  [456];
__device__ __align__(256) float g_JT [24 * 33];
__device__ __align__(256) float g_A2T[KQ * B];
__device__ __align__(256) float g_Rg [B * 288];
__device__ __align__(256) float g_P  [B * N2];

__constant__ int c_par[24] = {-1,0,0,0,1,2,3,4,5,6,7,8,9,9,9,12,13,14,16,17,18,19,20,21};

// ---------------------------------------------------------------------------
// buildEt: Et[n][v] (bf16 hi/lo). n<621: posedirs; 621..650: shapedirs;
//          651..653: v_template; 654: ones; else 0.
// ---------------------------------------------------------------------------
__global__ void k_buildEt(const float* __restrict__ posedirs,
                          const float* __restrict__ shapedirs,
                          const float* __restrict__ v_template) {
    int idx = blockIdx.x * blockDim.x + threadIdx.x;
    if (idx >= N1 * VP) return;
    int n = idx / VP, v = idx - n * VP;
    float val = 0.f;
    if (v < V) {
        if (n < 621) {
            int p = n / 3, c = n - 3 * p;
            val = posedirs[p * (V * 3) + 3 * v + c];
        } else if (n < 651) {
            int t = n - 621, q = t / 3, c = t - 3 * q;
            val = shapedirs[q * (V * 3) + 3 * v + c];
        } else if (n < 654) {
            val = v_template[3 * v + (n - 651)];
        } else if (n == 654) {
            val = 1.f;
        }
    }
    __nv_bfloat16 hi = __float2bfloat16(val);
    g_Eh[idx] = hi;
    g_El[idx] = __float2bfloat16(val - __bfloat162float(hi));
}

// ---------------------------------------------------------------------------
// buildGt: Gt[m][v] (bf16 hi/lo). m<456: jr*w; 456..479: Jreg; else 0.
// ---------------------------------------------------------------------------
__global__ void k_buildGt(const float* __restrict__ jr19,
                          const float* __restrict__ w24,
                          const float* __restrict__ Jreg24) {
    int idx = blockIdx.x * blockDim.x + threadIdx.x;
    if (idx >= M1 * VP) return;
    int m = idx / VP, v = idx - m * VP;
    float val = 0.f;
    if (v < V) {
        if (m < 456) {
            int k = m / 24, j = m - 24 * k;
            val = jr19[v * NK + k] * w24[v * NJ + j];
        } else if (m < 480) {
            val = Jreg24[v * NJ + (m - 456)];
        }
    }
    __nv_bfloat16 hi = __float2bfloat16(val);
    g_Gh[idx] = hi;
    g_Gl[idx] = __float2bfloat16(val - __bfloat162float(hi));
}

// ---------------------------------------------------------------------------
// GEMM1 on WMMA bf16: C[m][n] = sum_v G[m,v] * E[n,v], 3-term hi/lo emu.
// CTA tile 128x128, BK=32, 8 warps (2 m x 4 n), 64x32 per warp.
// Single smem buffer (40KB static), register prefetch (R1 pattern).
// Grid (N1/128=6, M1/128=4, SPLITK1=6).
// ---------------------------------------------------------------------------
__global__ void __launch_bounds__(256) k_gemm1_wmma() {
    using namespace nvcuda;

    __shared__ __align__(16) __nv_bfloat16 Ah[128][40];
    __shared__ __align__(16) __nv_bfloat16 Al[128][40];
    __shared__ __align__(16) __nv_bfloat16 Bh[128][40];
    __shared__ __align__(16) __nv_bfloat16 Bl[128][40];

    const int n0    = blockIdx.x * 128;
    const int m0    = blockIdx.y * 128;
    const int split = blockIdx.z;
    const int tid   = threadIdx.x;
    const int wid   = tid >> 5;
    const int wm    = (wid & 1) * 64;     // warp m-offset within tile
    const int wn    = (wid >> 1) * 32;    // warp n-offset within tile

    wmma::fragment<wmma::accumulator, 16, 16, 16, float> acc[4][2];
#pragma unroll
    for (int i = 0; i < 4; ++i)
#pragma unroll
        for (int j = 0; j < 2; ++j)
            wmma::fill_fragment(acc[i][j], 0.f);

    const int kbase = split * KSEG;
    const int nIter = KSEG / 32;          // 36

    // prefetch registers: 2 x uint4 per operand array per thread
    uint4 pAh[2], pAl[2], pBh[2], pBl[2];

#pragma unroll
    for (int i = 0; i < 2; ++i) {
        int linear = tid + 256 * i;
        int r = linear >> 2, c = (linear & 3) * 8;
        pAh[i] = *(const uint4*)(g_Gh + (size_t)(m0 + r) * VP + kbase + c);
        pAl[i] = *(const uint4*)(g_Gl + (size_t)(m0 + r) * VP + kbase + c);
        pBh[i] = *(const uint4*)(g_Eh + (size_t)(n0 + r) * VP + kbase + c);
        pBl[i] = *(const uint4*)(g_El + (size_t)(n0 + r) * VP + kbase + c);
    }

    for (int it = 0; it < nIter; ++it) {
        __syncthreads();
#pragma unroll
        for (int i = 0; i < 2; ++i) {
            int linear = tid + 256 * i;
            int r = linear >> 2, c = (linear & 3) * 8;
            *(uint4*)&Ah[r][c] = pAh[i];
            *(uint4*)&Al[r][c] = pAl[i];
            *(uint4*)&Bh[r][c] = pBh[i];
            *(uint4*)&Bl[r][c] = pBl[i];
        }
        __syncthreads();
        if (it + 1 < nIter) {
            int kk = kbase + (it + 1) * 32;
#pragma unroll
            for (int i = 0; i < 2; ++i) {
                int linear = tid + 256 * i;
                int r = linear >> 2, c = (linear & 3) * 8;
                pAh[i] = *(const uint4*)(g_Gh + (size_t)(m0 + r) * VP + kk + c);
                pAl[i] = *(const uint4*)(g_Gl + (size_t)(m0 + r) * VP + kk + c);
                pBh[i] = *(const uint4*)(g_Eh + (size_t)(n0 + r) * VP + kk + c);
                pBl[i] = *(const uint4*)(g_El + (size_t)(n0 + r) * VP + kk + c);
            }
        }
#pragma unroll
        for (int k0 = 0; k0 < 32; k0 += 16) {
            wmma::fragment<wmma::matrix_a, 16, 16, 16, __nv_bfloat16,
                           wmma::row_major> ah[4], al[4];
            wmma::fragment<wmma::matrix_b, 16, 16, 16, __nv_bfloat16,
                           wmma::col_major> bh[2], bl[2];
#pragma unroll
            for (int i = 0; i < 4; ++i) {
                wmma::load_matrix_sync(ah[i], &Ah[wm + i * 16][k0], 40);
                wmma::load_matrix_sync(al[i], &Al[wm + i * 16][k0], 40);
            }
#pragma unroll
            for (int j = 0; j < 2; ++j) {
                wmma::load_matrix_sync(bh[j], &Bh[wn + j * 16][k0], 40);
                wmma::load_matrix_sync(bl[j], &Bl[wn + j * 16][k0], 40);
            }
#pragma unroll
            for (int i = 0; i < 4; ++i)
#pragma unroll
                for (int j = 0; j < 2; ++j) {
                    wmma::mma_sync(acc[i][j], ah[i], bh[j], acc[i][j]);
                    wmma::mma_sync(acc[i][j], al[i], bh[j], acc[i][j]);
                    wmma::mma_sync(acc[i][j], ah[i], bl[j], acc[i][j]);
                }
        }
    }

    float* Co = g_Cp + (size_t)split * (M1 * N1);
#pragma unroll
    for (int i = 0; i < 4; ++i)
#pragma unroll
        for (int j = 0; j < 2; ++j)
            wmma::store_matrix_sync(
                &Co[(size_t)(m0 + wm + i * 16) * N1 + n0 + wn + j * 16],
                acc[i][j], N1, wmma::mem_row_major);
}

// ---------------------------------------------------------------------------
// Scalar 64x64 GEMM (proven R1) for GEMM2: C = A^T(K-major) @ B.
// ---------------------------------------------------------------------------
__global__ void k_gemm64(const float* __restrict__ A, int lda,
                         const float* __restrict__ B, int ldb,
                         float* __restrict__ C, int ldc, int kTotal) {
    const int row0 = blockIdx.y * 64;
    const int col0 = blockIdx.x * 64;

    __shared__ __align__(16) float As[16][64];
    __shared__ __align__(16) float Bs[16][64];

    const int tid = threadIdx.x;
    const int kk = tid >> 4;
    const int r4 = (tid & 15) << 2;
    const int tm = (tid >> 4) << 2;
    const int tn = (tid & 15) << 2;

    float acc[4][4] = {};

    const int nIter = kTotal >> 4;
    float4 ra = *(const float4*)&A[(size_t)kk * lda + row0 + r4];
    float4 rb = *(const float4*)&B[(size_t)kk * ldb + col0 + r4];

    for (int it = 0; it < nIter; ++it) {
        __syncthreads();
        *(float4*)&As[kk][r4] = ra;
        *(float4*)&Bs[kk][r4] = rb;
        __syncthreads();
        if (it + 1 < nIter) {
            int kb = (it + 1) * 16 + kk;
            ra = *(const float4*)&A[(size_t)kb * lda + row0 + r4];
            rb = *(const float4*)&B[(size_t)kb * ldb + col0 + r4];
        }
#pragma unroll
        for (int p = 0; p < 16; ++p) {
            float4 a = *(const float4*)&As[p][tm];
            float4 b = *(const float4*)&Bs[p][tn];
            float av[4] = {a.x, a.y, a.z, a.w};
            float bv[4] = {b.x, b.y, b.z, b.w};
#pragma unroll
            for (int i = 0; i < 4; ++i)
#pragma unroll
                for (int j = 0; j < 4; ++j)
                    acc[i][j] += av[i] * bv[j];
        }
    }

#pragma unroll
    for (int i = 0; i < 4; ++i) {
        float4 o = make_float4(acc[i][0], acc[i][1], acc[i][2], acc[i][3]);
        *(float4*)&C[(size_t)(row0 + tm + i) * ldc + col0 + tn] = o;
    }
}

// ---------------------------------------------------------------------------
// Reduce GEMM1 split-K partials into CT [q][m], S, JT.
// ---------------------------------------------------------------------------
__global__ void k_reduce() {
    int idx = blockIdx.x * blockDim.x + threadIdx.x;
    const int NCT = KQ * N2;
    if (idx < NCT) {
        int q = idx / N2, m = idx - q * N2;
        float val = 0.f;
        if (m < 1368 && q < 218) {
            int kj = m / 3, c = m - 3 * kj;
            int col;
            if (q == 0)        col = 651 + c;
            else if (q <= 10)  col = 621 + (q - 1) * 3 + c;
            else               col = (q - 11) * 3 + c;
            size_t off = (size_t)kj * N1 + col;
#pragma unroll
            for (int s = 0; s < SPLITK1; ++s)
                val += g_Cp[(size_t)s * (M1 * N1) + off];
        }
        g_CT[idx] = val;
    } else if (idx < NCT + 456) {
        int kj = idx - NCT;
        float val = 0.f;
#pragma unroll
        for (int s = 0; s < SPLITK1; ++s)
            val += g_Cp[(size_t)s * (M1 * N1) + (size_t)kj * N1 + 654];
        g_S[kj] = val;
    } else if (idx < NCT + 456 + 24 * 33) {
        int t2 = idx - NCT - 456;
        int j = t2 / 33, t = t2 - 33 * j;
        float val = 0.f;
#pragma unroll
        for (int s = 0; s < SPLITK1; ++s)
            val += g_Cp[(size_t)s * (M1 * N1) + (size_t)(456 + j) * N1 + 621 + t];
        g_JT[t2] = val;
    }
}

// ---------------------------------------------------------------------------
// Per-body prep (one warp / body): Rodrigues, J, A2T column, kinematic chain.
// ---------------------------------------------------------------------------
__global__ void k_prep(const float* __restrict__ beta,
                       const float* __restrict__ theta) {
    const int b = blockIdx.x;
    const int lane = threadIdx.x;

    __shared__ float Rsm[24][9];
    __shared__ float Jm[24][3];
    __shared__ float Ag[24][12];
    __shared__ float bet[10];

    if (lane < 10) bet[lane] = beta[b * NB + lane];
    __syncwarp();

    if (lane < 24) {
        float tx = theta[b * 72 + lane * 3 + 0];
        float ty = theta[b * 72 + lane * 3 + 1];
        float tz = theta[b * 72 + lane * 3 + 2];
        float ax = tx + 1e-8f, ay = ty + 1e-8f, az = tz + 1e-8f;
        float angle = sqrtf(ax * ax + ay * ay + az * az);
        float half = 0.5f * angle;
        float s = sinf(half), cw = cosf(half);
        float vx = tx / angle * s, vy = ty / angle * s, vz = tz / angle * s;
        float qn = sqrtf(cw * cw + vx * vx + vy * vy + vz * vz);
        float w = cw / qn, x = vx / qn, y = vy / qn, z = vz / qn;
        Rsm[lane][0] = 1.f - 2.f * (y * y + z * z);
        Rsm[lane][1] = 2.f * (x * y - w * z);
        Rsm[lane][2] = 2.f * (x * z + w * y);
        Rsm[lane][3] = 2.f * (x * y + w * z);
        Rsm[lane][4] = 1.f - 2.f * (x * x + z * z);
        Rsm[lane][5] = 2.f * (y * z - w * x);
        Rsm[lane][6] = 2.f * (x * z - w * y);
        Rsm[lane][7] = 2.f * (y * z + w * x);
        Rsm[lane][8] = 1.f - 2.f * (x * x + y * y);
#pragma unroll
        for (int c = 0; c < 3; ++c) {
            float val = g_JT[lane * 33 + 30 + c];
#pragma unroll
            for (int n = 0; n < 10; ++n)
                val += bet[n] * g_JT[lane * 33 + n * 3 + c];
            Jm[lane][c] = val;
        }
    }
    __syncwarp();

    for (int q = lane; q < KQ; q += 32) {
        float val;
        if (q == 0) val = 1.f;
        else if (q <= 10) val = bet[q - 1];
        else if (q < 218) {
            int p = q - 11;
            int i = p / 9 + 1, e = p - 9 * (p / 9);
            val = Rsm[i][e] - ((e == 0 || e == 4 || e == 8) ? 1.f : 0.f);
        } else val = 0.f;
        g_A2T[q * B + b] = val;
    }

    const int r = lane >> 2, cc = lane & 3;
    for (int i = 0; i < 24; ++i) {
        if (lane < 12) {
            float val;
            if (i == 0) {
                val = (cc < 3) ? Rsm[0][r * 3 + cc] * (cc == 0 ? 1.f : -1.f)
                               : Jm[0][r];
            } else {
                int par = c_par[i];
                float l0, l1, l2;
                if (cc < 3) {
                    l0 = Rsm[i][0 * 3 + cc];
                    l1 = Rsm[i][1 * 3 + cc];
                    l2 = Rsm[i][2 * 3 + cc];
                } else {
                    l0 = Jm[i][0] - Jm[par][0];
                    l1 = Jm[i][1] - Jm[par][1];
                    l2 = Jm[i][2] - Jm[par][2];
                }
                val = Ag[par][r * 4 + 0] * l0 + Ag[par][r * 4 + 1] * l1 +
                      Ag[par][r * 4 + 2] * l2;
                if (cc == 3) val += Ag[par][r * 4 + 3];
            }
            Ag[i][r * 4 + cc] = val;
        }
        __syncwarp();
    }

    for (int idx = lane; idx < 288; idx += 32) {
        int j = idx / 12, e = idx - 12 * j;
        float out;
        if (e < 9) {
            int rr = e / 3, c = e - 3 * rr;
            out = Ag[j][rr * 4 + c];
        } else {
            int rr = e - 9;
            out = Ag[j][rr * 4 + 3] -
                  (Ag[j][rr * 4 + 0] * Jm[j][0] + Ag[j][rr * 4 + 1] * Jm[j][1] +
                   Ag[j][rr * 4 + 2] * Jm[j][2]);
        }
        g_Rg[b * 288 + idx] = out;
    }
}

// ---------------------------------------------------------------------------
// joints epilogue
// ---------------------------------------------------------------------------
__global__ void k_joints(const float* __restrict__ trans,
                         float* __restrict__ out) {
    const int b = blockIdx.x;
    const int tid = threadIdx.x;
    __shared__ float sA[288];
    __shared__ float sS[456];
    for (int i = tid; i < 288; i += 64) sA[i] = g_Rg[b * 288 + i];
    for (int i = tid; i < 456; i += 64) sS[i] = g_S[i];
    __syncthreads();
    if (tid < 57) {
        int k = tid / 3, r = tid - 3 * k;
        float acc = trans[b * 3 + r];
        const float* Pb = &g_P[(size_t)b * N2];
#pragma unroll
        for (int j = 0; j < 24; ++j) {
            const float* M = &sA[j * 12];
            int m = (k * 24 + j) * 3;
            float p0 = Pb[m + 0], p1 = Pb[m + 1], p2 = Pb[m + 2];
            acc += M[r * 3 + 0] * p0 + M[r * 3 + 1] * p1 + M[r * 3 + 2] * p2 +
                   M[9 + r] * sS[k * 24 + j];
        }
        out[b * 57 + tid] = acc;
    }
}

} // namespace smpl

extern "C" void kernel_launch(void* const* d_in, const int* in_sizes, int n_in,
                              void* d_out, int out_size) {
    using namespace smpl;
    const float* beta       = (const float*)d_in[0];
    const float* theta      = (const float*)d_in[1];
    const float* trans      = (const float*)d_in[2];
    const float* v_template = (const float*)d_in[3];
    const float* shapedirs  = (const float*)d_in[4];
    const float* J_reg      = (const float*)d_in[5];
    const float* posedirs   = (const float*)d_in[6];
    const float* joint_reg  = (const float*)d_in[7];
    const float* weights    = (const float*)d_in[8];
    float* out = (float*)d_out;

    float *pCT, *pA2T, *pP;
    cudaGetSymbolAddress((void**)&pCT,  g_CT);
    cudaGetSymbolAddress((void**)&pA2T, g_A2T);
    cudaGetSymbolAddress((void**)&pP,   g_P);

    // 1) Build bf16 hi/lo operands
    {
        int n = N1 * VP;
        k_buildEt<<<(n + 255) / 256, 256>>>(posedirs, shapedirs, v_template);
    }
    {
        int n = M1 * VP;
        k_buildGt<<<(n + 255) / 256, 256>>>(joint_reg, weights, J_reg);
    }

    // 2) GEMM1 on WMMA bf16x3, split-K = 6
    {
        dim3 grid(N1 / 128, M1 / 128, SPLITK1);   // 6 x 4 x 6 = 144 CTAs
        k_gemm1_wmma<<<grid, 256>>>();
    }

    // 3) Reduce partials -> CT / S / JT
    {
        int n = KQ * N2 + 456 + 24 * 33;
        k_reduce<<<(n + 255) / 256, 256>>>();
    }

    // 4) Per-body prep
    k_prep<<<B, 32>>>(beta, theta);

    // 5) GEMM2: P = A2 @ CT (scalar, proven)
    {
        dim3 grid(N2 / 64, B / 64, 1);            // 22 x 16
        k_gemm64<<<grid, 256>>>(pA2T, B, pCT, N2, pP, N2, KQ);
    }

    // 6) Joints epilogue
    k_joints<<<B, 64>>>(trans, out);
}